// round 3
// baseline (speedup 1.0000x reference)
#include <cuda_runtime.h>
#include <math.h>

#define BB_ 2
#define S_  2048
#define D_  1024
#define H_  16
#define HD_ 64
#define M_  (BB_*S_)   // 4096

// Scratch (device globals; no allocation allowed)
__device__ float g_Q[BB_*H_*S_*HD_];
__device__ float g_K[BB_*H_*S_*HD_];
__device__ float g_V[BB_*H_*S_*HD_];
__device__ float g_attn[BB_*H_*S_*HD_];
__device__ float g_y[M_*D_];

// ---------------------------------------------------------------------------
// K1: QKV projection GEMM (out = x @ W^T + b), RoPE fused in epilogue.
// grid: (N/64=16, M/64=64, 3), block: 256 (16x16, 4x4 microtile)
// ---------------------------------------------------------------------------
__global__ void __launch_bounds__(256) gemm_qkv_kernel(
    const float* __restrict__ x,
    const float* __restrict__ Wq, const float* __restrict__ bq,
    const float* __restrict__ Wk, const float* __restrict__ bk,
    const float* __restrict__ Wv, const float* __restrict__ bv)
{
    __shared__ float As[16][68];
    __shared__ float Bs[16][68];

    const float* W; const float* bias; float* out; int do_rope;
    if (blockIdx.z == 0)      { W = Wq; bias = bq; out = g_Q; do_rope = 1; }
    else if (blockIdx.z == 1) { W = Wk; bias = bk; out = g_K; do_rope = 1; }
    else                      { W = Wv; bias = bv; out = g_V; do_rope = 0; }

    int tid = threadIdx.x;
    int tx = tid & 15, ty = tid >> 4;
    int m0 = blockIdx.y * 64, n0 = blockIdx.x * 64;
    int lm = tid >> 2;            // 0..63
    int lk = (tid & 3) * 4;       // 0,4,8,12

    const float* Ag = x + (size_t)(m0 + lm) * D_ + lk;
    const float* Bg = W + (size_t)(n0 + lm) * D_ + lk;

    float c[4][4] = {};

    for (int k0 = 0; k0 < D_; k0 += 16) {
        float4 a = *(const float4*)(Ag + k0);
        float4 b = *(const float4*)(Bg + k0);
        __syncthreads();
        As[lk+0][lm] = a.x; As[lk+1][lm] = a.y; As[lk+2][lm] = a.z; As[lk+3][lm] = a.w;
        Bs[lk+0][lm] = b.x; Bs[lk+1][lm] = b.y; Bs[lk+2][lm] = b.z; Bs[lk+3][lm] = b.w;
        __syncthreads();
        #pragma unroll
        for (int kk = 0; kk < 16; kk++) {
            float4 av = *(const float4*)&As[kk][ty*4];
            float4 bv4 = *(const float4*)&Bs[kk][tx*4];
            float aa[4] = {av.x, av.y, av.z, av.w};
            float bb[4] = {bv4.x, bv4.y, bv4.z, bv4.w};
            #pragma unroll
            for (int i = 0; i < 4; i++)
                #pragma unroll
                for (int j = 0; j < 4; j++)
                    c[i][j] = fmaf(aa[i], bb[j], c[i][j]);
        }
    }

    int n_base = n0 + tx * 4;
    int h  = n_base >> 6;
    int hd = n_base & 63;
    float4 bvec = *(const float4*)&bias[n_base];
    float bias4[4] = {bvec.x, bvec.y, bvec.z, bvec.w};

    const float NLOG = 0.28782313662425574f; // ln(10000)/32

    #pragma unroll
    for (int i = 0; i < 4; i++) {
        int m = m0 + ty * 4 + i;
        int bidx = m >> 11;
        int s = m & (S_ - 1);
        float v[4];
        #pragma unroll
        for (int j = 0; j < 4; j++) v[j] = c[i][j] + bias4[j];

        if (do_rope) {
            float sf = (float)s;
            #pragma unroll
            for (int p = 0; p < 4; p += 2) {
                int hd_e = (n_base + p) & 63;
                int hd_o = hd_e + 1;
                float fe = (float)(hd_e & 31);
                float fo = (float)(hd_o & 31);
                float the = sf * expf(-fe * NLOG);
                float tho = sf * expf(-fo * NLOG);
                float se, ce, so, co;
                sincosf(the, &se, &ce);
                sincosf(tho, &so, &co);
                float ve = v[p], vo = v[p+1];
                v[p]   = ve * ce - vo * se;
                v[p+1] = vo * co + ve * so;
            }
        }
        *(float4*)&out[(((size_t)bidx * H_ + h) * S_ + s) * HD_ + hd] =
            make_float4(v[0], v[1], v[2], v[3]);
    }
}

// ---------------------------------------------------------------------------
// K2: flash-style attention. grid: (S/64=32, B*H=32), block 256.
// Warp owns 8 q-rows; lane owns 2 k-cols / 2 hd-cols.
// ---------------------------------------------------------------------------
__global__ void __launch_bounds__(256) attn_kernel(
    const float* __restrict__ mask, const float* __restrict__ cwp)
{
    extern __shared__ float sm[];
    float* Qs  = sm;            // [64][64]
    float* KsT = sm + 4096;     // [kk=64][c=64]
    float* Vs  = sm + 8192;     // [c=64][hd=64]
    float* Ps  = sm + 12288;    // [64][66]

    int tid = threadIdx.x;
    int warp = tid >> 5, lane = tid & 31;
    int bh = blockIdx.y;
    int b  = bh >> 4;
    int q0 = blockIdx.x * 64;
    size_t headbase = (size_t)bh * S_ * HD_;
    float cw = *cwp;

    // stage Q
    for (int i = tid; i < 64 * 16; i += 256) {
        int r = i >> 4, kg = (i & 15) * 4;
        float4 qv = *(const float4*)&g_Q[headbase + (size_t)(q0 + r) * HD_ + kg];
        *(float4*)&Qs[r * 64 + kg] = qv;
    }

    float mprev[8], lsum[8], o0[8], o1[8];
    #pragma unroll
    for (int r = 0; r < 8; r++) { mprev[r] = -1e30f; lsum[r] = 0.f; o0[r] = 0.f; o1[r] = 0.f; }

    const float* maskb = mask + (size_t)b * S_ * S_;

    for (int k0 = 0; k0 < S_; k0 += 64) {
        __syncthreads();
        // stage K (transposed) and V
        for (int i = tid; i < 1024; i += 256) {
            int cc = i >> 4, kg = (i & 15) * 4;
            float4 kv = *(const float4*)&g_K[headbase + (size_t)(k0 + cc) * HD_ + kg];
            KsT[(kg+0)*64 + cc] = kv.x; KsT[(kg+1)*64 + cc] = kv.y;
            KsT[(kg+2)*64 + cc] = kv.z; KsT[(kg+3)*64 + cc] = kv.w;
            float4 vv = *(const float4*)&g_V[headbase + (size_t)(k0 + cc) * HD_ + kg];
            *(float4*)&Vs[cc * 64 + kg] = vv;
        }
        __syncthreads();

        // scores: s[r][2] for this lane's 2 k-columns
        float s0[8] = {}, s1[8] = {};
        for (int kk = 0; kk < 64; kk++) {
            float2 kv = *(const float2*)&KsT[kk * 64 + lane * 2];
            #pragma unroll
            for (int r = 0; r < 8; r++) {
                float q = Qs[(warp * 8 + r) * 64 + kk];
                s0[r] = fmaf(q, kv.x, s0[r]);
                s1[r] = fmaf(q, kv.y, s1[r]);
            }
        }

        // softmax (online) + write P
        #pragma unroll
        for (int r = 0; r < 8; r++) {
            int q = q0 + warp * 8 + r;
            float2 mk = *(const float2*)&maskb[(size_t)q * S_ + k0 + lane * 2];
            float v0 = s0[r] * 0.125f + mk.x * cw;
            float v1 = s1[r] * 0.125f + mk.y * cw;
            float tm = fmaxf(v0, v1);
            #pragma unroll
            for (int off = 16; off; off >>= 1)
                tm = fmaxf(tm, __shfl_xor_sync(0xffffffffu, tm, off));
            float nm = fmaxf(mprev[r], tm);
            float p0 = expf(v0 - nm), p1 = expf(v1 - nm);
            float corr = expf(mprev[r] - nm);
            mprev[r] = nm;
            float ts = p0 + p1;
            #pragma unroll
            for (int off = 16; off; off >>= 1)
                ts += __shfl_xor_sync(0xffffffffu, ts, off);
            lsum[r] = lsum[r] * corr + ts;
            o0[r] *= corr; o1[r] *= corr;
            *(float2*)&Ps[(warp * 8 + r) * 66 + lane * 2] = make_float2(p0, p1);
        }
        __syncwarp();

        // PV: O[r][hd] += P[r][c] * V[c][hd]
        for (int cc = 0; cc < 64; cc++) {
            float2 vv = *(const float2*)&Vs[cc * 64 + lane * 2];
            #pragma unroll
            for (int r = 0; r < 8; r++) {
                float p = Ps[(warp * 8 + r) * 66 + cc];
                o0[r] = fmaf(p, vv.x, o0[r]);
                o1[r] = fmaf(p, vv.y, o1[r]);
            }
        }
    }

    #pragma unroll
    for (int r = 0; r < 8; r++) {
        float inv = 1.0f / lsum[r];
        int q = q0 + warp * 8 + r;
        *(float2*)&g_attn[headbase + (size_t)q * HD_ + lane * 2] =
            make_float2(o0[r] * inv, o1[r] * inv);
    }
}

// ---------------------------------------------------------------------------
// K3: output projection (attn @ Wo^T + bo) + residual, gather from [B,H,S,HD]
// grid: (16, 64), block 256
// ---------------------------------------------------------------------------
__global__ void __launch_bounds__(256) gemm_out_kernel(
    const float* __restrict__ x,
    const float* __restrict__ Wo, const float* __restrict__ bo)
{
    __shared__ float As[16][68];
    __shared__ float Bs[16][68];

    int tid = threadIdx.x;
    int tx = tid & 15, ty = tid >> 4;
    int m0 = blockIdx.y * 64, n0 = blockIdx.x * 64;
    int lm = tid >> 2;
    int lk = (tid & 3) * 4;

    int mrow = m0 + lm;
    int bidx = mrow >> 11;
    int srow = mrow & (S_ - 1);
    const float* Bg = Wo + (size_t)(n0 + lm) * D_ + lk;

    float c[4][4] = {};

    for (int k0 = 0; k0 < D_; k0 += 16) {
        int k = k0 + lk;
        int h = k >> 6, hd = k & 63;
        float4 a = *(const float4*)&g_attn[(((size_t)bidx * H_ + h) * S_ + srow) * HD_ + hd];
        float4 b = *(const float4*)(Bg + k0);
        __syncthreads();
        As[lk+0][lm] = a.x; As[lk+1][lm] = a.y; As[lk+2][lm] = a.z; As[lk+3][lm] = a.w;
        Bs[lk+0][lm] = b.x; Bs[lk+1][lm] = b.y; Bs[lk+2][lm] = b.z; Bs[lk+3][lm] = b.w;
        __syncthreads();
        #pragma unroll
        for (int kk = 0; kk < 16; kk++) {
            float4 av = *(const float4*)&As[kk][ty*4];
            float4 bv4 = *(const float4*)&Bs[kk][tx*4];
            float aa[4] = {av.x, av.y, av.z, av.w};
            float bb2[4] = {bv4.x, bv4.y, bv4.z, bv4.w};
            #pragma unroll
            for (int i = 0; i < 4; i++)
                #pragma unroll
                for (int j = 0; j < 4; j++)
                    c[i][j] = fmaf(aa[i], bb2[j], c[i][j]);
        }
    }

    int n_base = n0 + tx * 4;
    float4 bvec = *(const float4*)&bo[n_base];

    #pragma unroll
    for (int i = 0; i < 4; i++) {
        int m = m0 + ty * 4 + i;
        float4 xr = *(const float4*)&x[(size_t)m * D_ + n_base];
        float4 yv = make_float4(c[i][0] + bvec.x + xr.x,
                                c[i][1] + bvec.y + xr.y,
                                c[i][2] + bvec.z + xr.z,
                                c[i][3] + bvec.w + xr.w);
        *(float4*)&g_y[(size_t)m * D_ + n_base] = yv;
    }
}

// ---------------------------------------------------------------------------
// K4: LayerNorm over last dim. grid: 4096 blocks, 256 threads (4 elems each)
// ---------------------------------------------------------------------------
__global__ void __launch_bounds__(256) ln_kernel(
    const float* __restrict__ gamma, const float* __restrict__ beta,
    float* __restrict__ out)
{
    __shared__ float red[256];
    __shared__ float sh_mu, sh_rs;
    int tid = threadIdx.x;
    size_t base = (size_t)blockIdx.x * D_;

    float4 v = *(const float4*)&g_y[base + tid * 4];
    red[tid] = v.x + v.y + v.z + v.w;
    __syncthreads();
    for (int off = 128; off; off >>= 1) {
        if (tid < off) red[tid] += red[tid + off];
        __syncthreads();
    }
    if (tid == 0) sh_mu = red[0] * (1.0f / D_);
    __syncthreads();
    float mu = sh_mu;

    float d0 = v.x - mu, d1 = v.y - mu, d2 = v.z - mu, d3 = v.w - mu;
    red[tid] = d0*d0 + d1*d1 + d2*d2 + d3*d3;
    __syncthreads();
    for (int off = 128; off; off >>= 1) {
        if (tid < off) red[tid] += red[tid + off];
        __syncthreads();
    }
    if (tid == 0) sh_rs = rsqrtf(red[0] * (1.0f / D_) + 1e-5f);
    __syncthreads();
    float rs = sh_rs;

    int n = tid * 4;
    float4 g = *(const float4*)&gamma[n];
    float4 bt = *(const float4*)&beta[n];
    float4 o = make_float4(d0 * rs * g.x + bt.x,
                           d1 * rs * g.y + bt.y,
                           d2 * rs * g.z + bt.z,
                           d3 * rs * g.w + bt.w);
    *(float4*)&out[base + n] = o;
}

// ---------------------------------------------------------------------------
extern "C" void kernel_launch(void* const* d_in, const int* in_sizes, int n_in,
                              void* d_out, int out_size)
{
    const float* x     = (const float*)d_in[0];
    const float* mask  = (const float*)d_in[1];
    const float* Wq    = (const float*)d_in[2];
    const float* bq    = (const float*)d_in[3];
    const float* Wk    = (const float*)d_in[4];
    const float* bk    = (const float*)d_in[5];
    const float* Wv    = (const float*)d_in[6];
    const float* bv    = (const float*)d_in[7];
    const float* Wo    = (const float*)d_in[8];
    const float* bo    = (const float*)d_in[9];
    const float* gamma = (const float*)d_in[10];
    const float* beta  = (const float*)d_in[11];
    const float* cw    = (const float*)d_in[12];
    float* out = (float*)d_out;

    const int ATTN_SMEM = (4096 + 4096 + 4096 + 64 * 66) * 4; // 66048 bytes
    cudaFuncSetAttribute(attn_kernel,
                         cudaFuncAttributeMaxDynamicSharedMemorySize, ATTN_SMEM);

    dim3 g1(D_ / 64, M_ / 64, 3);
    gemm_qkv_kernel<<<g1, 256>>>(x, Wq, bq, Wk, bk, Wv, bv);

    dim3 g2(S_ / 64, BB_ * H_);
    attn_kernel<<<g2, 256, ATTN_SMEM>>>(mask, cw);

    dim3 g3(D_ / 64, M_ / 64);
    gemm_out_kernel<<<g3, 256>>>(x, Wo, bo);

    ln_kernel<<<M_, 256>>>(gamma, beta, out);
}

// round 7
// speedup vs baseline: 1.5580x; 1.5580x over previous
#include <cuda_runtime.h>
#include <cuda_bf16.h>
#include <math.h>
#include <stdint.h>

#define BB_ 2
#define S_  2048
#define D_  1024
#define H_  16
#define HD_ 64
#define M_  (BB_*S_)     // 4096
#define KTOT (2*D_)      // 2048 (hi|lo concatenated K)

// ---------------------------------------------------------------------------
// Scratch (device globals; no allocation allowed)
// ---------------------------------------------------------------------------
__device__ float g_Q[BB_*H_*S_*HD_];
__device__ float g_K[BB_*H_*S_*HD_];
__device__ float g_V[BB_*H_*S_*HD_];
__device__ float g_y[M_*D_];
__device__ __nv_bfloat16 g_xc[M_*KTOT];       // x  hi|lo concat along K
__device__ __nv_bfloat16 g_wqc[D_*KTOT];
__device__ __nv_bfloat16 g_wkc[D_*KTOT];
__device__ __nv_bfloat16 g_wvc[D_*KTOT];
__device__ __nv_bfloat16 g_woc[D_*KTOT];
__device__ __nv_bfloat16 g_attnc[M_*KTOT];    // attention out hi|lo concat
__device__ float g_cos[S_*HD_];
__device__ float g_sin[S_*HD_];

// ---------------------------------------------------------------------------
// Helpers
// ---------------------------------------------------------------------------
__device__ __forceinline__ uint32_t smem_u32(const void* p) {
    uint32_t a;
    asm("{ .reg .u64 t; cvta.to.shared.u64 t, %1; cvt.u32.u64 %0, t; }" : "=r"(a) : "l"(p));
    return a;
}
__device__ __forceinline__ void cp16(uint32_t s, const void* g) {
    asm volatile("cp.async.cg.shared.global [%0], [%1], 16;" :: "r"(s), "l"(g));
}
__device__ __forceinline__ void ldsm4(uint32_t* r, uint32_t a) {
    asm volatile("ldmatrix.sync.aligned.m8n8.x4.shared.b16 {%0,%1,%2,%3}, [%4];"
                 : "=r"(r[0]), "=r"(r[1]), "=r"(r[2]), "=r"(r[3]) : "r"(a));
}
__device__ __forceinline__ void ldsm2(uint32_t* r, uint32_t a) {
    asm volatile("ldmatrix.sync.aligned.m8n8.x2.shared.b16 {%0,%1}, [%2];"
                 : "=r"(r[0]), "=r"(r[1]) : "r"(a));
}
__device__ __forceinline__ void mma16816(float* c, const uint32_t* a, const uint32_t* b) {
    asm volatile("mma.sync.aligned.m16n8k16.row.col.f32.bf16.bf16.f32 "
                 "{%0,%1,%2,%3}, {%4,%5,%6,%7}, {%8,%9}, {%0,%1,%2,%3};"
                 : "+f"(c[0]), "+f"(c[1]), "+f"(c[2]), "+f"(c[3])
                 : "r"(a[0]), "r"(a[1]), "r"(a[2]), "r"(a[3]), "r"(b[0]), "r"(b[1]));
}
// f32x2 packed helpers
__device__ __forceinline__ void ffma2(unsigned long long& d, unsigned long long a,
                                      unsigned long long b) {
    asm("fma.rn.f32x2 %0, %1, %2, %3;" : "=l"(d) : "l"(a), "l"(b), "l"(d));
}
__device__ __forceinline__ unsigned long long mul2(unsigned long long a, unsigned long long b) {
    unsigned long long d;
    asm("mul.rn.f32x2 %0, %1, %2;" : "=l"(d) : "l"(a), "l"(b));
    return d;
}
__device__ __forceinline__ unsigned long long pack2(float x, float y) {
    unsigned long long r;
    asm("mov.b64 %0, {%1, %2};" : "=l"(r) : "f"(x), "f"(y));
    return r;
}
__device__ __forceinline__ float2 unpack2(unsigned long long v) {
    float2 f;
    asm("mov.b64 {%0, %1}, %2;" : "=f"(f.x), "=f"(f.y) : "l"(v));
    return f;
}

// ---------------------------------------------------------------------------
// K0a: fp32 [R][1024] -> bf16 hi|lo concat [R][2048]
// ---------------------------------------------------------------------------
__global__ void __launch_bounds__(256) conv_kernel(
    const float* __restrict__ src, __nv_bfloat16* __restrict__ dst)
{
    size_t i = ((size_t)blockIdx.x * 256 + threadIdx.x) * 4;
    size_t r = i >> 10, c = i & 1023;
    float4 v = *(const float4*)(src + i);
    __nv_bfloat16 h0 = __float2bfloat16(v.x);
    __nv_bfloat16 h1 = __float2bfloat16(v.y);
    __nv_bfloat16 h2 = __float2bfloat16(v.z);
    __nv_bfloat16 h3 = __float2bfloat16(v.w);
    __nv_bfloat16 l0 = __float2bfloat16(v.x - __bfloat162float(h0));
    __nv_bfloat16 l1 = __float2bfloat16(v.y - __bfloat162float(h1));
    __nv_bfloat16 l2 = __float2bfloat16(v.z - __bfloat162float(h2));
    __nv_bfloat16 l3 = __float2bfloat16(v.w - __bfloat162float(h3));
    size_t hb = r * KTOT + c;
    *(__nv_bfloat162*)(dst + hb)            = __nv_bfloat162(h0, h1);
    *(__nv_bfloat162*)(dst + hb + 2)        = __nv_bfloat162(h2, h3);
    *(__nv_bfloat162*)(dst + hb + 1024)     = __nv_bfloat162(l0, l1);
    *(__nv_bfloat162*)(dst + hb + 1024 + 2) = __nv_bfloat162(l2, l3);
}

// ---------------------------------------------------------------------------
// K0b: RoPE sin/cos table
// ---------------------------------------------------------------------------
__global__ void rope_tab_kernel() {
    int s = blockIdx.x, hd = threadIdx.x;
    const float NLOG = 0.28782313662425574f; // ln(10000)/32
    float th = (float)s * expf(-(float)(hd & 31) * NLOG);
    float sv, cv;
    sincosf(th, &sv, &cv);
    g_cos[s * HD_ + hd] = cv;
    g_sin[s * HD_ + hd] = sv;
}

// ---------------------------------------------------------------------------
// mma.sync GEMM core: C[128,128] = A[128,2048] @ B[128,2048]^T (bf16, f32 acc)
// 256 threads = 8 warps (2x4), warp tile 64x32, BK=32, double-buffered cp.async
// ---------------------------------------------------------------------------
#define BKg 32
#define NKIT (KTOT / BKg)  // 64
#define ASTRIDE 40         // bf16 elements per smem row (80B, conflict-free ldmatrix)
#define OPBYTES (128 * ASTRIDE * 2)  // 10240 per operand per stage

__device__ __forceinline__ void gemm_loop(
    const __nv_bfloat16* __restrict__ Ab, const __nv_bfloat16* __restrict__ Bb,
    uint32_t base, float acc[4][4][4])
{
    int tid = threadIdx.x, lane = tid & 31, wid = tid >> 5;
    int wm = (wid >> 2) * 64, wn = (wid & 3) * 32;

    int r_ld = tid >> 1;                 // 0..127 (2 chunks of 16B per thread/operand)
    int c_ld = (tid & 1) * 2;            // chunk col 0/2 then +1

    auto ldst = [&](int st, int k0) {
        uint32_t sA = base + (uint32_t)(st * 2 + 0) * OPBYTES;
        uint32_t sB = base + (uint32_t)(st * 2 + 1) * OPBYTES;
        #pragma unroll
        for (int j = 0; j < 2; j++) {
            int c = c_ld + j;
            uint32_t so = (uint32_t)(r_ld * 80 + c * 16);
            cp16(sA + so, Ab + (size_t)r_ld * KTOT + k0 + c * 8);
            cp16(sB + so, Bb + (size_t)r_ld * KTOT + k0 + c * 8);
        }
        asm volatile("cp.async.commit_group;" ::: "memory");
    };

    ldst(0, 0);
    for (int kt = 0; kt < NKIT; kt++) {
        if (kt + 1 < NKIT) {
            ldst((kt + 1) & 1, (kt + 1) * BKg);
            asm volatile("cp.async.wait_group 1;" ::: "memory");
        } else {
            asm volatile("cp.async.wait_group 0;" ::: "memory");
        }
        __syncthreads();

        int st = kt & 1;
        uint32_t aB = base + (uint32_t)(st * 2 + 0) * OPBYTES;
        uint32_t bB = base + (uint32_t)(st * 2 + 1) * OPBYTES;
        int la = lane & 15, lka = (lane >> 4) << 3;
        int lb = lane & 7,  lkb = ((lane >> 3) & 1) << 3;

        #pragma unroll
        for (int ks = 0; ks < 2; ks++) {
            int kk = ks * 16;
            uint32_t afr[4][4], bfr[4][2];
            #pragma unroll
            for (int mi = 0; mi < 4; mi++)
                ldsm4(afr[mi], aB + (uint32_t)(((wm + mi * 16 + la) * ASTRIDE + kk + lka) * 2));
            #pragma unroll
            for (int ni = 0; ni < 4; ni++)
                ldsm2(bfr[ni], bB + (uint32_t)(((wn + ni * 8 + lb) * ASTRIDE + kk + lkb) * 2));
            #pragma unroll
            for (int mi = 0; mi < 4; mi++)
                #pragma unroll
                for (int ni = 0; ni < 4; ni++)
                    mma16816(acc[mi][ni], afr[mi], bfr[ni]);
        }
        __syncthreads();
    }
}

// ---------------------------------------------------------------------------
// K1: QKV projection (fused bias + RoPE). grid (8, 32, 3), block 256.
// ---------------------------------------------------------------------------
__global__ void __launch_bounds__(256, 2) qkv_mma_kernel(
    const float* __restrict__ bq, const float* __restrict__ bk,
    const float* __restrict__ bv)
{
    __shared__ __align__(16) __nv_bfloat16 sh[2 * 2 * 128 * ASTRIDE];

    const __nv_bfloat16* Wc;
    const float* bias;
    float* out;
    int dorope;
    if (blockIdx.z == 0)      { Wc = g_wqc; bias = bq; out = g_Q; dorope = 1; }
    else if (blockIdx.z == 1) { Wc = g_wkc; bias = bk; out = g_K; dorope = 1; }
    else                      { Wc = g_wvc; bias = bv; out = g_V; dorope = 0; }

    int m0 = blockIdx.y * 128, n0 = blockIdx.x * 128;
    float acc[4][4][4] = {};
    gemm_loop(g_xc + (size_t)m0 * KTOT, Wc + (size_t)n0 * KTOT, smem_u32(sh), acc);

    int lane = threadIdx.x & 31, wid = threadIdx.x >> 5;
    int wm = (wid >> 2) * 64, wn = (wid & 3) * 32;

    #pragma unroll
    for (int mi = 0; mi < 4; mi++) {
        #pragma unroll
        for (int ni = 0; ni < 4; ni++) {
            int cc0 = n0 + wn + ni * 8 + (lane & 3) * 2;
            int h = cc0 >> 6, hd0 = cc0 & 63;
            float2 bi = *(const float2*)&bias[cc0];
            #pragma unroll
            for (int rr = 0; rr < 2; rr++) {
                int r = m0 + wm + mi * 16 + (lane >> 2) + rr * 8;
                int bb = r >> 11, s = r & (S_ - 1);
                float v0 = acc[mi][ni][rr * 2 + 0] + bi.x;
                float v1 = acc[mi][ni][rr * 2 + 1] + bi.y;
                if (dorope) {
                    float2 cs = *(const float2*)&g_cos[s * HD_ + hd0];
                    float2 sn = *(const float2*)&g_sin[s * HD_ + hd0];
                    float t0 = v0 * cs.x - v1 * sn.x;
                    float t1 = v1 * cs.y + v0 * sn.y;
                    v0 = t0; v1 = t1;
                }
                *(float2*)&out[(((size_t)bb * H_ + h) * S_ + s) * HD_ + hd0] =
                    make_float2(v0, v1);
            }
        }
    }
}

// ---------------------------------------------------------------------------
// K3: output projection + bias + residual. grid (8, 32), block 256.
// ---------------------------------------------------------------------------
__global__ void __launch_bounds__(256, 2) out_mma_kernel(
    const float* __restrict__ x, const float* __restrict__ bo)
{
    __shared__ __align__(16) __nv_bfloat16 sh[2 * 2 * 128 * ASTRIDE];

    int m0 = blockIdx.y * 128, n0 = blockIdx.x * 128;
    float acc[4][4][4] = {};
    gemm_loop(g_attnc + (size_t)m0 * KTOT, g_woc + (size_t)n0 * KTOT, smem_u32(sh), acc);

    int lane = threadIdx.x & 31, wid = threadIdx.x >> 5;
    int wm = (wid >> 2) * 64, wn = (wid & 3) * 32;

    #pragma unroll
    for (int mi = 0; mi < 4; mi++) {
        #pragma unroll
        for (int ni = 0; ni < 4; ni++) {
            int cc0 = n0 + wn + ni * 8 + (lane & 3) * 2;
            float2 bi = *(const float2*)&bo[cc0];
            #pragma unroll
            for (int rr = 0; rr < 2; rr++) {
                int r = m0 + wm + mi * 16 + (lane >> 2) + rr * 8;
                float2 xr = *(const float2*)&x[(size_t)r * D_ + cc0];
                *(float2*)&g_y[(size_t)r * D_ + cc0] =
                    make_float2(acc[mi][ni][rr * 2 + 0] + bi.x + xr.x,
                                acc[mi][ni][rr * 2 + 1] + bi.y + xr.y);
            }
        }
    }
}

// ---------------------------------------------------------------------------
// K2: attention, f32x2 packed SIMT. grid (32, 32), block 256.
// Thread (ty=tid>>4, tx=tid&15) owns rows ty*4..+3, cols tx*4..+3 of 64x64 tile.
// ---------------------------------------------------------------------------
#define AP 68
#define ATTN_SMEM (4 * 64 * AP * 4)  // 69632

__global__ void __launch_bounds__(256, 2) attn_kernel(
    const float* __restrict__ mask, const float* __restrict__ cwp)
{
    extern __shared__ float sm[];
    float* QsT = sm;                 // [kk][q]
    float* KsT = sm + 64 * AP;       // [kk][kcol]
    float* Vs  = sm + 2 * 64 * AP;   // [kcol][hd]
    float* PsT = sm + 3 * 64 * AP;   // [kcol][q]

    int tid = threadIdx.x;
    int ty = tid >> 4, tx = tid & 15;
    int bh = blockIdx.y;
    int b = bh >> 4, h = bh & 15;
    int q0 = blockIdx.x * 64;
    size_t headbase = (size_t)bh * S_ * HD_;
    float cw = *cwp;
    const float* maskb = mask + (size_t)b * S_ * S_;

    for (int i = tid; i < 1024; i += 256) {
        int r = i >> 4, kg = (i & 15) * 4;
        float4 qv = *(const float4*)&g_Q[headbase + (size_t)(q0 + r) * HD_ + kg];
        QsT[(kg + 0) * AP + r] = qv.x;
        QsT[(kg + 1) * AP + r] = qv.y;
        QsT[(kg + 2) * AP + r] = qv.z;
        QsT[(kg + 3) * AP + r] = qv.w;
    }

    float mprev[4], lsum[4];
    unsigned long long o[4][2];
    #pragma unroll
    for (int i = 0; i < 4; i++) {
        mprev[i] = -1e30f; lsum[i] = 0.f; o[i][0] = 0ull; o[i][1] = 0ull;
    }

    for (int k0 = 0; k0 < S_; k0 += 64) {
        __syncthreads();
        for (int i = tid; i < 1024; i += 256) {
            int cc = i >> 4, kg = (i & 15) * 4;
            float4 kv = *(const float4*)&g_K[headbase + (size_t)(k0 + cc) * HD_ + kg];
            KsT[(kg + 0) * AP + cc] = kv.x;
            KsT[(kg + 1) * AP + cc] = kv.y;
            KsT[(kg + 2) * AP + cc] = kv.z;
            KsT[(kg + 3) * AP + cc] = kv.w;
            float4 vv = *(const float4*)&g_V[headbase + (size_t)(k0 + cc) * HD_ + kg];
            *(float4*)&Vs[cc * AP + kg] = vv;
        }
        __syncthreads();

        unsigned long long acc[4][2] = {};
        #pragma unroll 4
        for (int kk = 0; kk < 64; kk++) {
            float4 a = *(const float4*)&QsT[kk * AP + ty * 4];
            ulonglong2 bvv = *(const ulonglong2*)&KsT[kk * AP + tx * 4];
            unsigned long long a0 = pack2(a.x, a.x), a1 = pack2(a.y, a.y);
            unsigned long long a2 = pack2(a.z, a.z), a3 = pack2(a.w, a.w);
            ffma2(acc[0][0], a0, bvv.x); ffma2(acc[0][1], a0, bvv.y);
            ffma2(acc[1][0], a1, bvv.x); ffma2(acc[1][1], a1, bvv.y);
            ffma2(acc[2][0], a2, bvv.x); ffma2(acc[2][1], a2, bvv.y);
            ffma2(acc[3][0], a3, bvv.x); ffma2(acc[3][1], a3, bvv.y);
        }

        #pragma unroll
        for (int i = 0; i < 4; i++) {
            int q = q0 + ty * 4 + i;
            float2 v01 = unpack2(acc[i][0]);
            float2 v23 = unpack2(acc[i][1]);
            float4 mk = *(const float4*)&maskb[(size_t)q * S_ + k0 + tx * 4];
            float w0 = fmaf(mk.x, cw, v01.x * 0.125f);
            float w1 = fmaf(mk.y, cw, v01.y * 0.125f);
            float w2 = fmaf(mk.z, cw, v23.x * 0.125f);
            float w3 = fmaf(mk.w, cw, v23.y * 0.125f);
            float mx = fmaxf(fmaxf(w0, w1), fmaxf(w2, w3));
            #pragma unroll
            for (int off = 8; off; off >>= 1)
                mx = fmaxf(mx, __shfl_xor_sync(0xffffffffu, mx, off, 16));
            float nm = fmaxf(mprev[i], mx);
            float p0 = __expf(w0 - nm), p1 = __expf(w1 - nm);
            float p2 = __expf(w2 - nm), p3 = __expf(w3 - nm);
            float corr = __expf(mprev[i] - nm);
            mprev[i] = nm;
            float ts = (p0 + p1) + (p2 + p3);
            #pragma unroll
            for (int off = 8; off; off >>= 1)
                ts += __shfl_xor_sync(0xffffffffu, ts, off, 16);
            lsum[i] = lsum[i] * corr + ts;
            unsigned long long c2 = pack2(corr, corr);
            o[i][0] = mul2(o[i][0], c2);
            o[i][1] = mul2(o[i][1], c2);
            PsT[(tx * 4 + 0) * AP + ty * 4 + i] = p0;
            PsT[(tx * 4 + 1) * AP + ty * 4 + i] = p1;
            PsT[(tx * 4 + 2) * AP + ty * 4 + i] = p2;
            PsT[(tx * 4 + 3) * AP + ty * 4 + i] = p3;
        }
        __syncwarp();

        #pragma unroll 4
        for (int cc = 0; cc < 64; cc++) {
            float4 a = *(const float4*)&PsT[cc * AP + ty * 4];
            ulonglong2 bvv = *(const ulonglong2*)&Vs[cc * AP + tx * 4];
            unsigned long long a0 = pack2(a.x, a.x), a1 = pack2(a.y, a.y);
            unsigned long long a2 = pack2(a.z, a.z), a3 = pack2(a.w, a.w);
            ffma2(o[0][0], a0, bvv.x); ffma2(o[0][1], a0, bvv.y);
            ffma2(o[1][0], a1, bvv.x); ffma2(o[1][1], a1, bvv.y);
            ffma2(o[2][0], a2, bvv.x); ffma2(o[2][1], a2, bvv.y);
            ffma2(o[3][0], a3, bvv.x); ffma2(o[3][1], a3, bvv.y);
        }
    }

    // epilogue: normalize, split to bf16 hi|lo concat layout [m][2048]
    #pragma unroll
    for (int i = 0; i < 4; i++) {
        float inv = 1.0f / lsum[i];
        int q = q0 + ty * 4 + i;
        float2 o01 = unpack2(o[i][0]);
        float2 o23 = unpack2(o[i][1]);
        float v[4] = {o01.x * inv, o01.y * inv, o23.x * inv, o23.y * inv};
        size_t mrow = (size_t)b * S_ + q;
        size_t base = mrow * KTOT + h * HD_ + tx * 4;
        __nv_bfloat16 hh[4], ll[4];
        #pragma unroll
        for (int j = 0; j < 4; j++) {
            hh[j] = __float2bfloat16(v[j]);
            ll[j] = __float2bfloat16(v[j] - __bfloat162float(hh[j]));
        }
        *(__nv_bfloat162*)&g_attnc[base]            = __nv_bfloat162(hh[0], hh[1]);
        *(__nv_bfloat162*)&g_attnc[base + 2]        = __nv_bfloat162(hh[2], hh[3]);
        *(__nv_bfloat162*)&g_attnc[base + 1024]     = __nv_bfloat162(ll[0], ll[1]);
        *(__nv_bfloat162*)&g_attnc[base + 1024 + 2] = __nv_bfloat162(ll[2], ll[3]);
    }
}

// ---------------------------------------------------------------------------
// K4: LayerNorm over last dim. grid: 4096 blocks, 256 threads.
// ---------------------------------------------------------------------------
__global__ void __launch_bounds__(256) ln_kernel(
    const float* __restrict__ gamma, const float* __restrict__ beta,
    float* __restrict__ out)
{
    __shared__ float red[256];
    __shared__ float sh_mu, sh_rs;
    int tid = threadIdx.x;
    size_t base = (size_t)blockIdx.x * D_;

    float4 v = *(const float4*)&g_y[base + tid * 4];
    red[tid] = v.x + v.y + v.z + v.w;
    __syncthreads();
    for (int off = 128; off; off >>= 1) {
        if (tid < off) red[tid] += red[tid + off];
        __syncthreads();
    }
    if (tid == 0) sh_mu = red[0] * (1.0f / D_);
    __syncthreads();
    float mu = sh_mu;

    float d0 = v.x - mu, d1 = v.y - mu, d2 = v.z - mu, d3 = v.w - mu;
    red[tid] = d0 * d0 + d1 * d1 + d2 * d2 + d3 * d3;
    __syncthreads();
    for (int off = 128; off; off >>= 1) {
        if (tid < off) red[tid] += red[tid + off];
        __syncthreads();
    }
    if (tid == 0) sh_rs = rsqrtf(red[0] * (1.0f / D_) + 1e-5f);
    __syncthreads();
    float rs = sh_rs;

    int n = tid * 4;
    float4 g = *(const float4*)&gamma[n];
    float4 bt = *(const float4*)&beta[n];
    *(float4*)&out[base + n] = make_float4(d0 * rs * g.x + bt.x,
                                           d1 * rs * g.y + bt.y,
                                           d2 * rs * g.z + bt.z,
                                           d3 * rs * g.w + bt.w);
}

// ---------------------------------------------------------------------------
extern "C" void kernel_launch(void* const* d_in, const int* in_sizes, int n_in,
                              void* d_out, int out_size)
{
    const float* x     = (const float*)d_in[0];
    const float* mask  = (const float*)d_in[1];
    const float* Wq    = (const float*)d_in[2];
    const float* bq    = (const float*)d_in[3];
    const float* Wk    = (const float*)d_in[4];
    const float* bk    = (const float*)d_in[5];
    const float* Wv    = (const float*)d_in[6];
    const float* bv    = (const float*)d_in[7];
    const float* Wo    = (const float*)d_in[8];
    const float* bo    = (const float*)d_in[9];
    const float* gamma = (const float*)d_in[10];
    const float* beta  = (const float*)d_in[11];
    const float* cw    = (const float*)d_in[12];
    float* out = (float*)d_out;

    cudaFuncSetAttribute(attn_kernel,
                         cudaFuncAttributeMaxDynamicSharedMemorySize, ATTN_SMEM);

    __nv_bfloat16 *xc, *wqc, *wkc, *wvc, *woc;
    cudaGetSymbolAddress((void**)&xc,  g_xc);
    cudaGetSymbolAddress((void**)&wqc, g_wqc);
    cudaGetSymbolAddress((void**)&wkc, g_wkc);
    cudaGetSymbolAddress((void**)&wvc, g_wvc);
    cudaGetSymbolAddress((void**)&woc, g_woc);

    conv_kernel<<<M_ * D_ / 1024, 256>>>(x, xc);
    conv_kernel<<<D_ * D_ / 1024, 256>>>(Wq, wqc);
    conv_kernel<<<D_ * D_ / 1024, 256>>>(Wk, wkc);
    conv_kernel<<<D_ * D_ / 1024, 256>>>(Wv, wvc);
    conv_kernel<<<D_ * D_ / 1024, 256>>>(Wo, woc);
    rope_tab_kernel<<<S_, HD_>>>();

    qkv_mma_kernel<<<dim3(D_ / 128, M_ / 128, 3), 256>>>(bq, bk, bv);

    attn_kernel<<<dim3(S_ / 64, BB_ * H_), 256, ATTN_SMEM>>>(mask, cw);

    out_mma_kernel<<<dim3(D_ / 128, M_ / 128), 256>>>(x, bo);

    ln_kernel<<<M_, 256>>>(gamma, beta, out);
}

// round 9
// speedup vs baseline: 3.1871x; 2.0457x over previous
#include <cuda_runtime.h>
#include <cuda_bf16.h>
#include <math.h>
#include <stdint.h>

#define BB_ 2
#define S_  2048
#define D_  1024
#define H_  16
#define HD_ 64
#define M_  (BB_*S_)     // 4096
#define KTOT (2*D_)      // 2048 (hi|lo concatenated K)

// ---------------------------------------------------------------------------
// Scratch (device globals; no allocation allowed)
// ---------------------------------------------------------------------------
__device__ float g_y[M_*D_];
__device__ __nv_bfloat16 g_xc[M_*KTOT];       // x  hi|lo concat along K
__device__ __nv_bfloat16 g_wqc[D_*KTOT];
__device__ __nv_bfloat16 g_wkc[D_*KTOT];
__device__ __nv_bfloat16 g_wvc[D_*KTOT];
__device__ __nv_bfloat16 g_woc[D_*KTOT];
__device__ __nv_bfloat16 g_attnc[M_*KTOT];    // attention out hi|lo concat
__device__ __nv_bfloat16 g_qc[BB_*H_*S_*128]; // per-head Q bf16 [bh][s][hi64|lo64]
__device__ __nv_bfloat16 g_kc[BB_*H_*S_*128];
__device__ __nv_bfloat16 g_vc[BB_*H_*S_*128];
__device__ float g_cos[S_*HD_];
__device__ float g_sin[S_*HD_];

// ---------------------------------------------------------------------------
// Helpers
// ---------------------------------------------------------------------------
__device__ __forceinline__ uint32_t smem_u32(const void* p) {
    uint32_t a;
    asm("{ .reg .u64 t; cvta.to.shared.u64 t, %1; cvt.u32.u64 %0, t; }" : "=r"(a) : "l"(p));
    return a;
}
__device__ __forceinline__ void cp16(uint32_t s, const void* g) {
    asm volatile("cp.async.cg.shared.global [%0], [%1], 16;" :: "r"(s), "l"(g));
}
__device__ __forceinline__ void ldsm4(uint32_t* r, uint32_t a) {
    asm volatile("ldmatrix.sync.aligned.m8n8.x4.shared.b16 {%0,%1,%2,%3}, [%4];"
                 : "=r"(r[0]), "=r"(r[1]), "=r"(r[2]), "=r"(r[3]) : "r"(a));
}
__device__ __forceinline__ void ldsm4t(uint32_t* r, uint32_t a) {
    asm volatile("ldmatrix.sync.aligned.m8n8.x4.trans.shared.b16 {%0,%1,%2,%3}, [%4];"
                 : "=r"(r[0]), "=r"(r[1]), "=r"(r[2]), "=r"(r[3]) : "r"(a));
}
__device__ __forceinline__ void ldsm2(uint32_t* r, uint32_t a) {
    asm volatile("ldmatrix.sync.aligned.m8n8.x2.shared.b16 {%0,%1}, [%2];"
                 : "=r"(r[0]), "=r"(r[1]) : "r"(a));
}
__device__ __forceinline__ void mma16816(float* c, const uint32_t* a, const uint32_t* b) {
    asm volatile("mma.sync.aligned.m16n8k16.row.col.f32.bf16.bf16.f32 "
                 "{%0,%1,%2,%3}, {%4,%5,%6,%7}, {%8,%9}, {%0,%1,%2,%3};"
                 : "+f"(c[0]), "+f"(c[1]), "+f"(c[2]), "+f"(c[3])
                 : "r"(a[0]), "r"(a[1]), "r"(a[2]), "r"(a[3]), "r"(b[0]), "r"(b[1]));
}
// pack two fp32 into bf16x2 hi (rounded) and lo (residual) words
__device__ __forceinline__ void split2(float v0, float v1, uint32_t& hi, uint32_t& lo) {
    __nv_bfloat16 h0 = __float2bfloat16(v0), h1 = __float2bfloat16(v1);
    float l0 = v0 - __bfloat162float(h0), l1 = v1 - __bfloat162float(h1);
    __nv_bfloat162 hp(h0, h1);
    __nv_bfloat162 lp(__float2bfloat16(l0), __float2bfloat16(l1));
    hi = *reinterpret_cast<uint32_t*>(&hp);
    lo = *reinterpret_cast<uint32_t*>(&lp);
}

// ---------------------------------------------------------------------------
// K0a: fp32 [R][1024] -> bf16 hi|lo concat [R][2048]
// ---------------------------------------------------------------------------
__global__ void __launch_bounds__(256) conv_kernel(
    const float* __restrict__ src, __nv_bfloat16* __restrict__ dst)
{
    size_t i = ((size_t)blockIdx.x * 256 + threadIdx.x) * 4;
    size_t r = i >> 10, c = i & 1023;
    float4 v = *(const float4*)(src + i);
    uint32_t h01, l01, h23, l23;
    split2(v.x, v.y, h01, l01);
    split2(v.z, v.w, h23, l23);
    size_t hb = r * KTOT + c;
    *(uint32_t*)(&dst[hb])            = h01;
    *(uint32_t*)(&dst[hb + 2])        = h23;
    *(uint32_t*)(&dst[hb + 1024])     = l01;
    *(uint32_t*)(&dst[hb + 1024 + 2]) = l23;
}

// ---------------------------------------------------------------------------
// K0b: RoPE sin/cos table
// ---------------------------------------------------------------------------
__global__ void rope_tab_kernel() {
    int s = blockIdx.x, hd = threadIdx.x;
    const float NLOG = 0.28782313662425574f; // ln(10000)/32
    float th = (float)s * expf(-(float)(hd & 31) * NLOG);
    float sv, cv;
    sincosf(th, &sv, &cv);
    g_cos[s * HD_ + hd] = cv;
    g_sin[s * HD_ + hd] = sv;
}

// ---------------------------------------------------------------------------
// mma.sync GEMM core: C[128,128] = A[128,2048] @ B[128,2048]^T (bf16, f32 acc)
// ---------------------------------------------------------------------------
#define BKg 32
#define NKIT (KTOT / BKg)  // 64
#define ASTRIDE 40
#define OPBYTES (128 * ASTRIDE * 2)

__device__ __forceinline__ void gemm_loop(
    const __nv_bfloat16* __restrict__ Ab, const __nv_bfloat16* __restrict__ Bb,
    uint32_t base, float acc[4][4][4])
{
    int tid = threadIdx.x, lane = tid & 31, wid = tid >> 5;
    int wm = (wid >> 2) * 64, wn = (wid & 3) * 32;

    int r_ld = tid >> 1;
    int c_ld = (tid & 1) * 2;

    auto ldst = [&](int st, int k0) {
        uint32_t sA = base + (uint32_t)(st * 2 + 0) * OPBYTES;
        uint32_t sB = base + (uint32_t)(st * 2 + 1) * OPBYTES;
        #pragma unroll
        for (int j = 0; j < 2; j++) {
            int c = c_ld + j;
            uint32_t so = (uint32_t)(r_ld * 80 + c * 16);
            cp16(sA + so, Ab + (size_t)r_ld * KTOT + k0 + c * 8);
            cp16(sB + so, Bb + (size_t)r_ld * KTOT + k0 + c * 8);
        }
        asm volatile("cp.async.commit_group;" ::: "memory");
    };

    ldst(0, 0);
    for (int kt = 0; kt < NKIT; kt++) {
        if (kt + 1 < NKIT) {
            ldst((kt + 1) & 1, (kt + 1) * BKg);
            asm volatile("cp.async.wait_group 1;" ::: "memory");
        } else {
            asm volatile("cp.async.wait_group 0;" ::: "memory");
        }
        __syncthreads();

        int st = kt & 1;
        uint32_t aB = base + (uint32_t)(st * 2 + 0) * OPBYTES;
        uint32_t bB = base + (uint32_t)(st * 2 + 1) * OPBYTES;
        int la = lane & 15, lka = (lane >> 4) << 3;
        int lb = lane & 7,  lkb = ((lane >> 3) & 1) << 3;

        #pragma unroll
        for (int ks = 0; ks < 2; ks++) {
            int kk = ks * 16;
            uint32_t afr[4][4], bfr[4][2];
            #pragma unroll
            for (int mi = 0; mi < 4; mi++)
                ldsm4(afr[mi], aB + (uint32_t)(((wm + mi * 16 + la) * ASTRIDE + kk + lka) * 2));
            #pragma unroll
            for (int ni = 0; ni < 4; ni++)
                ldsm2(bfr[ni], bB + (uint32_t)(((wn + ni * 8 + lb) * ASTRIDE + kk + lkb) * 2));
            #pragma unroll
            for (int mi = 0; mi < 4; mi++)
                #pragma unroll
                for (int ni = 0; ni < 4; ni++)
                    mma16816(acc[mi][ni], afr[mi], bfr[ni]);
        }
        __syncthreads();
    }
}

// ---------------------------------------------------------------------------
// K1: QKV projection (fused bias + RoPE), writes bf16 hi|lo per-head layout.
// grid (8, 32, 3), block 256.
// ---------------------------------------------------------------------------
__global__ void __launch_bounds__(256, 2) qkv_mma_kernel(
    const float* __restrict__ bq, const float* __restrict__ bk,
    const float* __restrict__ bv)
{
    __shared__ __align__(16) __nv_bfloat16 sh[2 * 2 * 128 * ASTRIDE];

    const __nv_bfloat16* Wc;
    const float* bias;
    __nv_bfloat16* outc;
    int dorope;
    if (blockIdx.z == 0)      { Wc = g_wqc; bias = bq; outc = g_qc; dorope = 1; }
    else if (blockIdx.z == 1) { Wc = g_wkc; bias = bk; outc = g_kc; dorope = 1; }
    else                      { Wc = g_wvc; bias = bv; outc = g_vc; dorope = 0; }

    int m0 = blockIdx.y * 128, n0 = blockIdx.x * 128;
    float acc[4][4][4] = {};
    gemm_loop(g_xc + (size_t)m0 * KTOT, Wc + (size_t)n0 * KTOT, smem_u32(sh), acc);

    int lane = threadIdx.x & 31, wid = threadIdx.x >> 5;
    int wm = (wid >> 2) * 64, wn = (wid & 3) * 32;

    #pragma unroll
    for (int mi = 0; mi < 4; mi++) {
        #pragma unroll
        for (int ni = 0; ni < 4; ni++) {
            int cc0 = n0 + wn + ni * 8 + (lane & 3) * 2;
            int h = cc0 >> 6, hd0 = cc0 & 63;
            float2 bi = *(const float2*)&bias[cc0];
            #pragma unroll
            for (int rr = 0; rr < 2; rr++) {
                int r = m0 + wm + mi * 16 + (lane >> 2) + rr * 8;
                int bb = r >> 11, s = r & (S_ - 1);
                float v0 = acc[mi][ni][rr * 2 + 0] + bi.x;
                float v1 = acc[mi][ni][rr * 2 + 1] + bi.y;
                if (dorope) {
                    float2 cs = *(const float2*)&g_cos[s * HD_ + hd0];
                    float2 sn = *(const float2*)&g_sin[s * HD_ + hd0];
                    float t0 = v0 * cs.x - v1 * sn.x;
                    float t1 = v1 * cs.y + v0 * sn.y;
                    v0 = t0; v1 = t1;
                }
                uint32_t hw, lw;
                split2(v0, v1, hw, lw);
                size_t rowb = ((size_t)(bb * H_ + h) * S_ + s) * 128 + hd0;
                *(uint32_t*)&outc[rowb]      = hw;
                *(uint32_t*)&outc[rowb + 64] = lw;
            }
        }
    }
}

// ---------------------------------------------------------------------------
// K2: attention via mma.sync bf16. grid (16, 32), block 256 (8 warps x 16 q).
// smem: Q[128][136] + double-buffered K/V[64][136] tiles. shift-0 softmax.
// ---------------------------------------------------------------------------
#define ATTN_SMEM_N (34816 + 2 * 34816)  // 104448

__global__ void __launch_bounds__(256, 1) attn_kernel(
    const float* __restrict__ mask, const float* __restrict__ cwp)
{
    extern __shared__ char smc[];
    uint32_t sb = smem_u32(smc);
    int tid = threadIdx.x, lane = tid & 31, wid = tid >> 5;
    int bh = blockIdx.y, b = bh >> 4, h = bh & 15;
    int q0 = blockIdx.x * 128;
    const __nv_bfloat16* Qg = g_qc + ((size_t)bh * S_ + q0) * 128;
    const __nv_bfloat16* Kg = g_kc + (size_t)bh * S_ * 128;
    const __nv_bfloat16* Vg = g_vc + (size_t)bh * S_ * 128;
    float cw = *cwp;
    const float* maskb = mask + (size_t)b * S_ * S_;

    // prefetch Q (whole 128x128 bf16 block), then tile 0 (K+V)
    for (int i = tid; i < 2048; i += 256) {
        int r = i >> 4, c = i & 15;
        cp16(sb + r * 272 + c * 16, Qg + (size_t)r * 128 + c * 8);
    }
    asm volatile("cp.async.commit_group;" ::: "memory");
    for (int i = tid; i < 1024; i += 256) {
        int r = i >> 4, c = i & 15;
        cp16(sb + 34816u + r * 272 + c * 16, Kg + (size_t)r * 128 + c * 8);
        cp16(sb + 34816u + 17408u + r * 272 + c * 16, Vg + (size_t)r * 128 + c * 8);
    }
    asm volatile("cp.async.commit_group;" ::: "memory");
    asm volatile("cp.async.wait_group 0;" ::: "memory");
    __syncthreads();

    // Q fragments: A[16q][128 concat-hd] per warp, resident for whole loop
    uint32_t aQ[8][4];
    {
        uint32_t qa = sb + (uint32_t)((wid * 16 + (lane & 15)) * 272 + ((lane >> 4) << 4));
        #pragma unroll
        for (int j = 0; j < 8; j++) ldsm4(aQ[j], qa + j * 32);
    }

    float oacc[8][4];
    #pragma unroll
    for (int n = 0; n < 8; n++) {
        oacc[n][0] = oacc[n][1] = oacc[n][2] = oacc[n][3] = 0.f;
    }
    float ls0 = 0.f, ls1 = 0.f;
    int r0q = q0 + wid * 16 + (lane >> 2);

    for (int kt = 0; kt < 32; kt++) {
        if (kt > 0) {
            asm volatile("cp.async.wait_group 0;" ::: "memory");
            __syncthreads();
        }
        if (kt + 1 < 32) {
            int stn = (kt + 1) & 1;
            uint32_t kb = sb + 34816u + (uint32_t)stn * 34816u;
            const __nv_bfloat16* Kp = Kg + (size_t)(kt + 1) * 64 * 128;
            const __nv_bfloat16* Vp = Vg + (size_t)(kt + 1) * 64 * 128;
            for (int i = tid; i < 1024; i += 256) {
                int r = i >> 4, c = i & 15;
                cp16(kb + r * 272 + c * 16, Kp + (size_t)r * 128 + c * 8);
                cp16(kb + 17408u + r * 272 + c * 16, Vp + (size_t)r * 128 + c * 8);
            }
            asm volatile("cp.async.commit_group;" ::: "memory");
        }
        int st = kt & 1;
        uint32_t Kb = sb + 34816u + (uint32_t)st * 34816u;
        uint32_t Vb = Kb + 17408u;

        // ---- QK^T: scores s[8 kcol-ntiles][4] over 128-concat hd
        float s[8][4];
        #pragma unroll
        for (int n = 0; n < 8; n++)
            s[n][0] = s[n][1] = s[n][2] = s[n][3] = 0.f;

        uint32_t kbase = Kb + (uint32_t)((((lane & 7) + ((lane >> 4) & 1) * 8) * 272)
                                         + ((lane >> 3) & 1) * 16);
        #pragma unroll
        for (int j = 0; j < 8; j++) {
            #pragma unroll
            for (int np = 0; np < 4; np++) {
                uint32_t bf[4];
                ldsm4(bf, kbase + (uint32_t)(np * (16 * 272) + j * 32));
                mma16816(s[2 * np],     aQ[j], bf);
                mma16816(s[2 * np + 1], aQ[j], bf + 2);
            }
        }

        // ---- softmax (shift=0): p = exp(s/8 + mask*cw); P -> bf16 hi/lo frags
        uint32_t Pa[8], Pb[8], PaL[8], PbL[8];
        {
            int kcol0 = kt * 64 + (lane & 3) * 2;
            const float* mrow0 = maskb + (size_t)r0q * S_ + kcol0;
            const float* mrow1 = mrow0 + 8 * S_;
            #pragma unroll
            for (int n = 0; n < 8; n++) {
                float2 m0 = *(const float2*)(mrow0 + n * 8);
                float2 m1 = *(const float2*)(mrow1 + n * 8);
                float p0 = __expf(fmaf(m0.x, cw, s[n][0] * 0.125f));
                float p1 = __expf(fmaf(m0.y, cw, s[n][1] * 0.125f));
                float p2 = __expf(fmaf(m1.x, cw, s[n][2] * 0.125f));
                float p3 = __expf(fmaf(m1.y, cw, s[n][3] * 0.125f));
                ls0 += p0 + p1; ls1 += p2 + p3;
                split2(p0, p1, Pa[n], PaL[n]);
                split2(p2, p3, Pb[n], PbL[n]);
            }
        }

        // ---- P @ V: [Phi|Phi|Plo] x [Vhi|Vlo|Vhi], V via ldmatrix.trans
        uint32_t vbase = Vb + (uint32_t)((((lane & 7) + ((lane >> 3) & 1) * 8) * 272)
                                         + ((lane >> 4) & 1) * 16);
        #pragma unroll
        for (int js = 0; js < 4; js++) {
            uint32_t aPf[4]  = {Pa[2 * js],  Pb[2 * js],  Pa[2 * js + 1],  Pb[2 * js + 1]};
            uint32_t aPlf[4] = {PaL[2 * js], PbL[2 * js], PaL[2 * js + 1], PbL[2 * js + 1]};
            #pragma unroll
            for (int nh = 0; nh < 4; nh++) {
                uint32_t vf[4];
                ldsm4t(vf, vbase + (uint32_t)(js * (16 * 272) + nh * 32));
                mma16816(oacc[2 * nh],     aPf,  vf);
                mma16816(oacc[2 * nh + 1], aPf,  vf + 2);
                mma16816(oacc[2 * nh],     aPlf, vf);
                mma16816(oacc[2 * nh + 1], aPlf, vf + 2);
                uint32_t vl[4];
                ldsm4t(vl, vbase + (uint32_t)(js * (16 * 272) + nh * 32 + 128));
                mma16816(oacc[2 * nh],     aPf, vl);
                mma16816(oacc[2 * nh + 1], aPf, vl + 2);
            }
        }
    }

    // ---- epilogue: row sums, normalize, write bf16 hi|lo concat
    ls0 += __shfl_xor_sync(0xffffffffu, ls0, 1);
    ls0 += __shfl_xor_sync(0xffffffffu, ls0, 2);
    ls1 += __shfl_xor_sync(0xffffffffu, ls1, 1);
    ls1 += __shfl_xor_sync(0xffffffffu, ls1, 2);
    float inv0 = 1.0f / ls0, inv1 = 1.0f / ls1;

    size_t row0 = (size_t)(b * S_ + r0q) * KTOT;
    size_t row1 = row0 + (size_t)8 * KTOT;
    int colh = h * 64 + (lane & 3) * 2;
    #pragma unroll
    for (int n = 0; n < 8; n++) {
        int cc = colh + n * 8;
        uint32_t h0w, l0w, h1w, l1w;
        split2(oacc[n][0] * inv0, oacc[n][1] * inv0, h0w, l0w);
        split2(oacc[n][2] * inv1, oacc[n][3] * inv1, h1w, l1w);
        *(uint32_t*)&g_attnc[row0 + cc]        = h0w;
        *(uint32_t*)&g_attnc[row0 + 1024 + cc] = l0w;
        *(uint32_t*)&g_attnc[row1 + cc]        = h1w;
        *(uint32_t*)&g_attnc[row1 + 1024 + cc] = l1w;
    }
}

// ---------------------------------------------------------------------------
// K3: output projection + bias + residual. grid (8, 32), block 256.
// ---------------------------------------------------------------------------
__global__ void __launch_bounds__(256, 2) out_mma_kernel(
    const float* __restrict__ x, const float* __restrict__ bo)
{
    __shared__ __align__(16) __nv_bfloat16 sh[2 * 2 * 128 * ASTRIDE];

    int m0 = blockIdx.y * 128, n0 = blockIdx.x * 128;
    float acc[4][4][4] = {};
    gemm_loop(g_attnc + (size_t)m0 * KTOT, g_woc + (size_t)n0 * KTOT, smem_u32(sh), acc);

    int lane = threadIdx.x & 31, wid = threadIdx.x >> 5;
    int wm = (wid >> 2) * 64, wn = (wid & 3) * 32;

    #pragma unroll
    for (int mi = 0; mi < 4; mi++) {
        #pragma unroll
        for (int ni = 0; ni < 4; ni++) {
            int cc0 = n0 + wn + ni * 8 + (lane & 3) * 2;
            float2 bi = *(const float2*)&bo[cc0];
            #pragma unroll
            for (int rr = 0; rr < 2; rr++) {
                int r = m0 + wm + mi * 16 + (lane >> 2) + rr * 8;
                float2 xr = *(const float2*)&x[(size_t)r * D_ + cc0];
                *(float2*)&g_y[(size_t)r * D_ + cc0] =
                    make_float2(acc[mi][ni][rr * 2 + 0] + bi.x + xr.x,
                                acc[mi][ni][rr * 2 + 1] + bi.y + xr.y);
            }
        }
    }
}

// ---------------------------------------------------------------------------
// K4: LayerNorm over last dim. grid 4096, block 256.
// ---------------------------------------------------------------------------
__global__ void __launch_bounds__(256) ln_kernel(
    const float* __restrict__ gamma, const float* __restrict__ beta,
    float* __restrict__ out)
{
    __shared__ float red[256];
    __shared__ float sh_mu, sh_rs;
    int tid = threadIdx.x;
    size_t base = (size_t)blockIdx.x * D_;

    float4 v = *(const float4*)&g_y[base + tid * 4];
    red[tid] = v.x + v.y + v.z + v.w;
    __syncthreads();
    for (int off = 128; off; off >>= 1) {
        if (tid < off) red[tid] += red[tid + off];
        __syncthreads();
    }
    if (tid == 0) sh_mu = red[0] * (1.0f / D_);
    __syncthreads();
    float mu = sh_mu;

    float d0 = v.x - mu, d1 = v.y - mu, d2 = v.z - mu, d3 = v.w - mu;
    red[tid] = d0 * d0 + d1 * d1 + d2 * d2 + d3 * d3;
    __syncthreads();
    for (int off = 128; off; off >>= 1) {
        if (tid < off) red[tid] += red[tid + off];
        __syncthreads();
    }
    if (tid == 0) sh_rs = rsqrtf(red[0] * (1.0f / D_) + 1e-5f);
    __syncthreads();
    float rs = sh_rs;

    int n = tid * 4;
    float4 g = *(const float4*)&gamma[n];
    float4 bt = *(const float4*)&beta[n];
    *(float4*)&out[base + n] = make_float4(d0 * rs * g.x + bt.x,
                                           d1 * rs * g.y + bt.y,
                                           d2 * rs * g.z + bt.z,
                                           d3 * rs * g.w + bt.w);
}

// ---------------------------------------------------------------------------
extern "C" void kernel_launch(void* const* d_in, const int* in_sizes, int n_in,
                              void* d_out, int out_size)
{
    const float* x     = (const float*)d_in[0];
    const float* mask  = (const float*)d_in[1];
    const float* Wq    = (const float*)d_in[2];
    const float* bq    = (const float*)d_in[3];
    const float* Wk    = (const float*)d_in[4];
    const float* bk    = (const float*)d_in[5];
    const float* Wv    = (const float*)d_in[6];
    const float* bv    = (const float*)d_in[7];
    const float* Wo    = (const float*)d_in[8];
    const float* bo    = (const float*)d_in[9];
    const float* gamma = (const float*)d_in[10];
    const float* beta  = (const float*)d_in[11];
    const float* cw    = (const float*)d_in[12];
    float* out = (float*)d_out;

    cudaFuncSetAttribute(attn_kernel,
                         cudaFuncAttributeMaxDynamicSharedMemorySize, ATTN_SMEM_N);

    __nv_bfloat16 *xc, *wqc, *wkc, *wvc, *woc;
    cudaGetSymbolAddress((void**)&xc,  g_xc);
    cudaGetSymbolAddress((void**)&wqc, g_wqc);
    cudaGetSymbolAddress((void**)&wkc, g_wkc);
    cudaGetSymbolAddress((void**)&wvc, g_wvc);
    cudaGetSymbolAddress((void**)&woc, g_woc);

    conv_kernel<<<M_ * D_ / 1024, 256>>>(x, xc);
    conv_kernel<<<D_ * D_ / 1024, 256>>>(Wq, wqc);
    conv_kernel<<<D_ * D_ / 1024, 256>>>(Wk, wkc);
    conv_kernel<<<D_ * D_ / 1024, 256>>>(Wv, wvc);
    conv_kernel<<<D_ * D_ / 1024, 256>>>(Wo, woc);
    rope_tab_kernel<<<S_, HD_>>>();

    qkv_mma_kernel<<<dim3(D_ / 128, M_ / 128, 3), 256>>>(bq, bk, bv);

    attn_kernel<<<dim3(S_ / 128, BB_ * H_), 256, ATTN_SMEM_N>>>(mask, cw);

    out_mma_kernel<<<dim3(D_ / 128, M_ / 128), 256>>>(x, bo);

    ln_kernel<<<M_, 256>>>(gamma, beta, out);
}